// round 16
// baseline (speedup 1.0000x reference)
#include <cuda_runtime.h>
#include <cuda_bf16.h>
#include <cstdint>

#define B_   8
#define N_   1024
#define NIN_ 64
#define H_   128
#define F_   192

typedef unsigned long long u64;

// ---------------- scratch (device globals) ----------------
__device__ __align__(16) char g_Wsw_hi[2 * 49152];   // W sides, 384B-pitch swizzled
__device__ __align__(16) char g_Wsw_lo[2 * 49152];
__device__ __align__(16) char g_WbT_hi[2 * 32768];   // W_bil^T per k, 256B-pitch swizzled
__device__ __align__(16) char g_WbT_lo[2 * 32768];
__device__ __align__(16) __nv_bfloat16 g_hlb_hi[B_ * N_ * H_];
__device__ __align__(16) __nv_bfloat16 g_hlb_lo[B_ * N_ * H_];
__device__ __align__(16) __nv_bfloat16 g_hr_hi[B_ * N_ * H_];
__device__ __align__(16) __nv_bfloat16 g_hr_lo[B_ * N_ * H_];
__device__ __align__(16) __nv_bfloat16 g_t_hi[2 * B_ * N_ * H_];
__device__ __align__(16) __nv_bfloat16 g_t_lo[2 * B_ * N_ * H_];
// int8 hi/lo planes + per-row scales (built by quant_kernel)
__device__ __align__(16) int8_t g_t8a[2 * B_ * N_ * H_];
__device__ __align__(16) int8_t g_t8b[2 * B_ * N_ * H_];
__device__ __align__(16) int8_t g_hr8a[B_ * N_ * H_];
__device__ __align__(16) int8_t g_hr8b[B_ * N_ * H_];
__device__ float g_t8s[2 * B_ * N_];
__device__ float g_hr8s[B_ * N_];

__device__ __forceinline__ uint32_t smem_u32(const void* p) {
    uint32_t a;
    asm("{ .reg .u64 t; cvta.to.shared.u64 t, %1; cvt.u32.u64 %0, t; }" : "=r"(a) : "l"(p));
    return a;
}
// ---------------- tensor-core primitives (no 'a'-suffix PTX) ----------------
__device__ __forceinline__ void ldsm4(uint32_t& a0, uint32_t& a1, uint32_t& a2, uint32_t& a3, uint32_t addr) {
    asm volatile("ldmatrix.sync.aligned.m8n8.x4.shared.b16 {%0,%1,%2,%3}, [%4];"
        : "=r"(a0), "=r"(a1), "=r"(a2), "=r"(a3) : "r"(addr));
}
__device__ __forceinline__ void ldsm2(uint32_t& b0, uint32_t& b1, uint32_t addr) {
    asm volatile("ldmatrix.sync.aligned.m8n8.x2.shared.b16 {%0,%1}, [%2];"
        : "=r"(b0), "=r"(b1) : "r"(addr));
}
__device__ __forceinline__ void mma_bf16(float* c, const uint32_t* a, const uint32_t* b) {
    asm volatile("mma.sync.aligned.m16n8k16.row.col.f32.bf16.bf16.f32 "
        "{%0,%1,%2,%3}, {%4,%5,%6,%7}, {%8,%9}, {%0,%1,%2,%3};"
        : "+f"(c[0]), "+f"(c[1]), "+f"(c[2]), "+f"(c[3])
        : "r"(a[0]), "r"(a[1]), "r"(a[2]), "r"(a[3]), "r"(b[0]), "r"(b[1]));
}
__device__ __forceinline__ void mma_s8(int* c, const uint32_t* a, const uint32_t* b) {
    asm volatile("mma.sync.aligned.m16n8k32.row.col.s32.s8.s8.s32 "
        "{%0,%1,%2,%3}, {%4,%5,%6,%7}, {%8,%9}, {%0,%1,%2,%3};"
        : "+r"(c[0]), "+r"(c[1]), "+r"(c[2]), "+r"(c[3])
        : "r"(a[0]), "r"(a[1]), "r"(a[2]), "r"(a[3]), "r"(b[0]), "r"(b[1]));
}
__device__ __forceinline__ void split_bf16(float v, __nv_bfloat16& hi, __nv_bfloat16& lo) {
    hi = __float2bfloat16_rn(v);
    lo = __float2bfloat16_rn(v - __bfloat162float(hi));
}
// ---------------- cp.async ----------------
__device__ __forceinline__ void cp16(uint32_t dst, const void* src) {
    asm volatile("cp.async.cg.shared.global [%0], [%1], 16;" :: "r"(dst), "l"(src));
}
__device__ __forceinline__ void cp_commit() { asm volatile("cp.async.commit_group;" ::: "memory"); }
__device__ __forceinline__ void cp_wait0()  { asm volatile("cp.async.wait_group 0;" ::: "memory"); }

// =====================================================================
// prep: W -> bf16 hi/lo planes, pre-swizzled (unchanged)
// =====================================================================
__global__ __launch_bounds__(256)
void prep_kernel(const float* __restrict__ Wl, const float* __restrict__ Wr,
                 const float* __restrict__ Wbil)
{
    const int t = blockIdx.x * 256 + threadIdx.x;
    if (t < 2 * H_ * F_) {
        int side = t / (H_ * F_), r = t % (H_ * F_);
        int h = r / F_, f = r % F_;
        float v = (side ? Wr : Wl)[r];
        __nv_bfloat16 hi, lo; split_bf16(v, hi, lo);
        uint32_t byte = (uint32_t)h * 384u + (((uint32_t)f * 2u) ^ (((uint32_t)h & 7u) << 4));
        *(__nv_bfloat16*)(g_Wsw_hi + side * 49152 + byte) = hi;
        *(__nv_bfloat16*)(g_Wsw_lo + side * 49152 + byte) = lo;
    } else if (t < 2 * H_ * F_ + 2 * H_ * H_) {
        int r = t - 2 * H_ * F_;
        int k = r / (H_ * H_), rr = r % (H_ * H_);
        int g = rr / H_, h = rr % H_;
        float v = Wbil[k * H_ * H_ + h * H_ + g];
        __nv_bfloat16 hi, lo; split_bf16(v, hi, lo);
        uint32_t byte = (uint32_t)g * 256u + (((uint32_t)h * 2u) ^ (((uint32_t)g & 7u) << 4));
        *(__nv_bfloat16*)(g_WbT_hi + k * 32768 + byte) = hi;
        *(__nv_bfloat16*)(g_WbT_lo + k * 32768 + byte) = lo;
    }
}

// =====================================================================
// Kernel A (HMMA, unchanged)
// =====================================================================
#define HP 49152

__global__ __launch_bounds__(256, 1)
void hidden_kernel(const float* __restrict__ x,
                   const float* __restrict__ bl, const float* __restrict__ br)
{
    extern __shared__ char smc[];
    const int i0   = blockIdx.x * 128;
    const int b    = blockIdx.y;
    const int side = blockIdx.z;
    const int tid  = threadIdx.x;

    {
        const uint4* sh = (const uint4*)(g_Wsw_hi + side * HP);
        const uint4* sl = (const uint4*)(g_Wsw_lo + side * HP);
        uint4* dh = (uint4*)(smc + 2 * HP);
        uint4* dl = (uint4*)(smc + 3 * HP);
        #pragma unroll
        for (int it = 0; it < 12; it++) {
            dh[tid + it * 256] = sh[tid + it * 256];
            dl[tid + it * 256] = sl[tid + it * 256];
        }
    }
    const float* xb = x + (size_t)b * N_ * NIN_;
    #pragma unroll
    for (int seg = 0; seg < 3; seg++) {
        const int off = (seg == 0) ? 0 : (((seg == 1) == (side == 0)) ? -1 : 1);
        #pragma unroll 4
        for (int it = 0; it < 16; it++) {
            int idx = tid + it * 256;
            int m = idx >> 5, cp = idx & 31;
            int gi = i0 + m + off;
            float2 v = (gi >= 0 && gi < N_) ? *(const float2*)(xb + gi * NIN_ + cp * 2)
                                            : make_float2(0.f, 0.f);
            __nv_bfloat16 h0, l0, h1, l1;
            split_bf16(v.x, h0, l0); split_bf16(v.y, h1, l1);
            uint32_t byte = (uint32_t)m * 384u +
                (((uint32_t)(seg * 128 + cp * 4)) ^ (((uint32_t)m & 7u) << 4));
            *(__nv_bfloat162*)(smc + byte)      = __nv_bfloat162(h0, h1);
            *(__nv_bfloat162*)(smc + HP + byte) = __nv_bfloat162(l0, l1);
        }
    }
    __syncthreads();

    const int warp = tid >> 5, lane = tid & 31;
    const int wm = warp >> 2, wn = warp & 3;
    const int arowl = wm * 64 + ((lane >> 3) & 1) * 8 + (lane & 7);
    const uint32_t acoff = (lane >> 4) * 16;
    const uint32_t asw = (arowl & 7) << 4;
    const uint32_t abase = (uint32_t)arowl * 384;
    const int l16 = lane & 15;
    const int browl = wn * 32 + (l16 & 7);
    const uint32_t bcoff = ((l16 >> 3) & 1) * 16;
    const uint32_t bsw = (browl & 7) << 4;
    const uint32_t bbase = (uint32_t)browl * 384;

    const uint32_t sb = smem_u32(smc);
    const uint32_t pAhi = sb, pAlo = sb + HP, pBhi = sb + 2 * HP, pBlo = sb + 3 * HP;

    float acc[4][4][4];
    #pragma unroll
    for (int mi = 0; mi < 4; mi++)
        #pragma unroll
        for (int ni = 0; ni < 4; ni++)
            #pragma unroll
            for (int e = 0; e < 4; e++) acc[mi][ni][e] = 0.f;

    #pragma unroll 1
    for (int pass = 0; pass < 3; pass++) {
        const uint32_t pa = (pass == 2) ? pAlo : pAhi;
        const uint32_t pb = (pass == 1) ? pBlo : pBhi;
        #pragma unroll 4
        for (int ks = 0; ks < 12; ks++) {
            const uint32_t kcol = (uint32_t)ks * 32;
            uint32_t a[4][4], bf[4][2];
            #pragma unroll
            for (int mi = 0; mi < 4; mi++)
                ldsm4(a[mi][0], a[mi][1], a[mi][2], a[mi][3],
                      pa + abase + mi * 16 * 384 + ((kcol + acoff) ^ asw));
            #pragma unroll
            for (int ni = 0; ni < 4; ni++)
                ldsm2(bf[ni][0], bf[ni][1],
                      pb + bbase + ni * 8 * 384 + ((kcol + bcoff) ^ bsw));
            #pragma unroll
            for (int mi = 0; mi < 4; mi++)
                #pragma unroll
                for (int ni = 0; ni < 4; ni++)
                    mma_bf16(acc[mi][ni], a[mi], bf[ni]);
        }
    }

    const int crow = lane >> 2, cj = lane & 3;
    const float* bias = side ? br : bl;
    __nv_bfloat16* dhi = side ? g_hr_hi : g_hlb_hi;
    __nv_bfloat16* dlo = side ? g_hr_lo : g_hlb_lo;
    #pragma unroll
    for (int mi = 0; mi < 4; mi++) {
        #pragma unroll
        for (int ni = 0; ni < 4; ni++) {
            const int h0 = wn * 32 + ni * 8 + 2 * cj;
            const float2 bv = *(const float2*)(bias + h0);
            #pragma unroll
            for (int half = 0; half < 2; half++) {
                const int r = wm * 64 + mi * 16 + crow + half * 8;
                float v0 = fmaxf(acc[mi][ni][2 * half + 0] + bv.x, 0.f);
                float v1 = fmaxf(acc[mi][ni][2 * half + 1] + bv.y, 0.f);
                __nv_bfloat16 h0b, l0b, h1b, l1b;
                split_bf16(v0, h0b, l0b); split_bf16(v1, h1b, l1b);
                const size_t o = ((size_t)b * N_ + i0 + r) * H_ + h0;
                *(__nv_bfloat162*)(dhi + o) = __nv_bfloat162(h0b, h1b);
                *(__nv_bfloat162*)(dlo + o) = __nv_bfloat162(l0b, l1b);
            }
        }
    }
}

// =====================================================================
// Kernel B (HMMA, unchanged)
// =====================================================================
#define PB 32768

__device__ __forceinline__ void load_plane(char* dst, const __nv_bfloat16* src, int tid)
{
    const uint4* s = (const uint4*)src;
    #pragma unroll
    for (int it = 0; it < 8; it++) {
        int idx = tid + it * 256;
        int row = idx >> 4, c16 = idx & 15;
        uint32_t byte = row * 256 + ((c16 * 16) ^ ((row & 7) << 4));
        *(uint4*)(dst + byte) = s[idx];
    }
}

__global__ __launch_bounds__(256, 1)
void tform_kernel()
{
    extern __shared__ char smc[];
    const int i0 = blockIdx.x * 128;
    const int b  = blockIdx.y;
    const int k  = blockIdx.z;
    const int tid = threadIdx.x;

    const size_t arow = ((size_t)b * N_ + i0) * H_;
    load_plane(smc + 0 * PB, g_hlb_hi + arow, tid);
    load_plane(smc + 1 * PB, g_hlb_lo + arow, tid);
    {
        const uint4* sh = (const uint4*)(g_WbT_hi + k * PB);
        const uint4* sl = (const uint4*)(g_WbT_lo + k * PB);
        uint4* dh = (uint4*)(smc + 2 * PB);
        uint4* dl = (uint4*)(smc + 3 * PB);
        #pragma unroll
        for (int it = 0; it < 8; it++) {
            dh[tid + it * 256] = sh[tid + it * 256];
            dl[tid + it * 256] = sl[tid + it * 256];
        }
    }
    __syncthreads();

    const int warp = tid >> 5, lane = tid & 31;
    const int wm = warp >> 2, wn = warp & 3;
    const int arowl = wm * 64 + ((lane >> 3) & 1) * 8 + (lane & 7);
    const uint32_t acoff = (lane >> 4) * 16;
    const uint32_t asw = (arowl & 7) << 4;
    const uint32_t abase = (uint32_t)arowl * 256;
    const int l16 = lane & 15;
    const int browl = wn * 32 + (l16 & 7);
    const uint32_t bcoff = ((l16 >> 3) & 1) * 16;
    const uint32_t bsw = (browl & 7) << 4;
    const uint32_t bbase = (uint32_t)browl * 256;

    const uint32_t sb = smem_u32(smc);
    const uint32_t pAhi = sb, pAlo = sb + PB, pBhi = sb + 2 * PB, pBlo = sb + 3 * PB;

    float acc[4][4][4];
    #pragma unroll
    for (int mi = 0; mi < 4; mi++)
        #pragma unroll
        for (int ni = 0; ni < 4; ni++)
            #pragma unroll
            for (int e = 0; e < 4; e++) acc[mi][ni][e] = 0.f;

    #pragma unroll 1
    for (int pass = 0; pass < 3; pass++) {
        const uint32_t pa = (pass == 2) ? pAlo : pAhi;
        const uint32_t pb = (pass == 1) ? pBlo : pBhi;
        #pragma unroll 4
        for (int ks = 0; ks < 8; ks++) {
            const uint32_t kcol = (uint32_t)ks * 32;
            uint32_t a[4][4], bf[4][2];
            #pragma unroll
            for (int mi = 0; mi < 4; mi++)
                ldsm4(a[mi][0], a[mi][1], a[mi][2], a[mi][3],
                      pa + abase + mi * 4096 + ((kcol + acoff) ^ asw));
            #pragma unroll
            for (int ni = 0; ni < 4; ni++)
                ldsm2(bf[ni][0], bf[ni][1],
                      pb + bbase + ni * 2048 + ((kcol + bcoff) ^ bsw));
            #pragma unroll
            for (int mi = 0; mi < 4; mi++)
                #pragma unroll
                for (int ni = 0; ni < 4; ni++)
                    mma_bf16(acc[mi][ni], a[mi], bf[ni]);
        }
    }

    const int crow = lane >> 2, cj = lane & 3;
    __nv_bfloat16* dhi = g_t_hi + (size_t)k * B_ * N_ * H_;
    __nv_bfloat16* dlo = g_t_lo + (size_t)k * B_ * N_ * H_;
    #pragma unroll
    for (int mi = 0; mi < 4; mi++) {
        #pragma unroll
        for (int ni = 0; ni < 4; ni++) {
            const int g0 = wn * 32 + ni * 8 + 2 * cj;
            #pragma unroll
            for (int half = 0; half < 2; half++) {
                const int r = wm * 64 + mi * 16 + crow + half * 8;
                float v0 = acc[mi][ni][2 * half + 0];
                float v1 = acc[mi][ni][2 * half + 1];
                __nv_bfloat16 h0b, l0b, h1b, l1b;
                split_bf16(v0, h0b, l0b); split_bf16(v1, h1b, l1b);
                const size_t o = ((size_t)b * N_ + i0 + r) * H_ + g0;
                *(__nv_bfloat162*)(dhi + o) = __nv_bfloat162(h0b, h1b);
                *(__nv_bfloat162*)(dlo + o) = __nv_bfloat162(l0b, l1b);
            }
        }
    }
}

// =====================================================================
// quant: bf16 hi/lo planes -> int8 a/b planes + per-row scale.
//   v ≈ s*(a*128 + b),  s = rowmax/16256.  Warp per row; lane owns 4 cols.
//   rows 0..16383 = t (k-major), 16384..24575 = hr.
// =====================================================================
__global__ __launch_bounds__(256)
void quant_kernel()
{
    const int w = blockIdx.x * 8 + (threadIdx.x >> 5);   // 24576 warps
    const int lane = threadIdx.x & 31;
    const __nv_bfloat16 *hi, *lo;
    int8_t *pa, *pb; float* ps; int row;
    if (w < 16384) { hi = g_t_hi;  lo = g_t_lo;  pa = g_t8a;  pb = g_t8b;  ps = g_t8s;  row = w; }
    else           { hi = g_hr_hi; lo = g_hr_lo; pa = g_hr8a; pb = g_hr8b; ps = g_hr8s; row = w - 16384; }

    const size_t base = (size_t)row * H_ + lane * 4;
    float v[4];
    {
        __nv_bfloat162 ha = *(const __nv_bfloat162*)(hi + base);
        __nv_bfloat162 hb = *(const __nv_bfloat162*)(hi + base + 2);
        __nv_bfloat162 la = *(const __nv_bfloat162*)(lo + base);
        __nv_bfloat162 lb = *(const __nv_bfloat162*)(lo + base + 2);
        v[0] = __bfloat162float(ha.x) + __bfloat162float(la.x);
        v[1] = __bfloat162float(ha.y) + __bfloat162float(la.y);
        v[2] = __bfloat162float(hb.x) + __bfloat162float(lb.x);
        v[3] = __bfloat162float(hb.y) + __bfloat162float(lb.y);
    }
    float m = fmaxf(fmaxf(fabsf(v[0]), fabsf(v[1])), fmaxf(fabsf(v[2]), fabsf(v[3])));
    #pragma unroll
    for (int o = 16; o >= 1; o >>= 1) m = fmaxf(m, __shfl_xor_sync(0xFFFFFFFFu, m, o));
    const float inv = (m > 0.f) ? 16256.f / m : 0.f;

    uint32_t pkA = 0, pkB = 0;
    #pragma unroll
    for (int e = 0; e < 4; e++) {
        int X = __float2int_rn(v[e] * inv);
        int A = __float2int_rn((float)X * 0.0078125f);
        A = max(-127, min(127, A));
        int Bq = X - (A << 7);
        pkA |= ((uint32_t)A  & 0xFFu) << (e * 8);
        pkB |= ((uint32_t)Bq & 0xFFu) << (e * 8);
    }
    ((uint32_t*)pa)[(size_t)row * 32 + lane] = pkA;
    ((uint32_t*)pb)[(size_t)row * 32 + lane] = pkB;
    if (lane == 0) ps[row] = m * (1.f / 16256.f);
}

// =====================================================================
// Kernel C v5: int8 pipelined pair GEMM, 512 threads, 4x4 warps.
//   out_k = s_t*s_hr*(16384*Aa·Ba + 128*(Aa·Bb + Ab·Ba)) + bias
//   s8 m16n8k32 MMA; frags via ldmatrix.b16 on 128B-pitch swizzled planes.
//   smem: Ba 16K | Bb 16K | Abuf0 32K | Abuf1 32K = 96KB.
// =====================================================================
#define PAIR_SMEM 98304
#define AP8 8192              // 64 rows x 128B sub-plane

__device__ __forceinline__ void issue_A8(uint32_t dstbase, int b, int i0c, int tid)
{
    #pragma unroll
    for (int it = 0; it < 4; it++) {
        int idx = tid + it * 512;                 // 2048 x 16B
        int sub = idx >> 9;                       // 0..3 : k0a,k0b,k1a,k1b
        int k = sub >> 1, p = sub & 1;
        int r = (idx >> 3) & 63, c16 = idx & 7;
        const int8_t* src = (p ? g_t8b : g_t8a)
            + ((size_t)(k * 8192 + b * 1024 + i0c + r)) * 128 + c16 * 16;
        uint32_t dst = dstbase + sub * AP8 + r * 128 + ((c16 * 16) ^ ((r & 7) << 4));
        cp16(dst, src);
    }
}

__global__ __launch_bounds__(512, 1)
void pair_kernel(const float* __restrict__ bbil, float2* __restrict__ out)
{
    extern __shared__ char smc[];
    const uint32_t sbase = smem_u32(smc);
    const int j0    = blockIdx.x * 128;
    const int b     = blockIdx.y;
    const int ihalf = blockIdx.z;
    const int tid = threadIdx.x;
    const int warp = tid >> 5, lane = tid & 31;
    const int wm = warp >> 2, wn = warp & 3;     // 4(m) x 4(n)

    // --- B planes (hr a/b int8) via cp.async, swizzled, 128B pitch ---
    {
        #pragma unroll
        for (int it = 0; it < 4; it++) {
            int idx = tid + it * 512;             // 2048 x 16B
            int p = idx >> 10;                    // 0 a, 1 b
            int r = (idx >> 3) & 127, c16 = idx & 7;
            const int8_t* src = (p ? g_hr8b : g_hr8a)
                + ((size_t)(b * 1024 + j0 + r)) * 128 + c16 * 16;
            uint32_t dst = sbase + p * 16384 + r * 128 + ((c16 * 16) ^ ((r & 7) << 4));
            cp16(dst, src);
        }
    }
    issue_A8(sbase + 32768, b, ihalf * 512, tid);
    cp_commit();

    // lane geometry (128B pitch)
    const int arowl = wm * 16 + ((lane >> 3) & 1) * 8 + (lane & 7);
    const uint32_t acoff = (lane >> 4) * 16;
    const uint32_t asw = (arowl & 7) << 4;
    const uint32_t abase = (uint32_t)arowl * 128;
    const int l16 = lane & 15;
    const int browl = wn * 32 + (l16 & 7);
    const uint32_t bcoff = ((l16 >> 3) & 1) * 16;
    const uint32_t bsw = (browl & 7) << 4;
    const uint32_t bbase = (uint32_t)browl * 128;
    const uint32_t pBa = sbase, pBb = sbase + 16384;

    const float bb0 = bbil[0], bb1 = bbil[1];
    const int crow = lane >> 2, cj = lane & 3;

    #pragma unroll 1
    for (int c = 0; c < 8; c++) {
        cp_wait0();
        __syncthreads();                           // buf[c&1] full, prior reads done
        if (c < 7) {
            issue_A8(sbase + 32768 + ((c + 1) & 1) * 32768, b, ihalf * 512 + (c + 1) * 64, tid);
            cp_commit();
        }
        const uint32_t Abuf = sbase + 32768 + (c & 1) * 32768;

        int acc1[2][4][4], acc2[2][4][4];          // [k][ni][elem]
        #pragma unroll
        for (int k = 0; k < 2; k++)
            #pragma unroll
            for (int ni = 0; ni < 4; ni++)
                #pragma unroll
                for (int e = 0; e < 4; e++) { acc1[k][ni][e] = 0; acc2[k][ni][e] = 0; }

        #pragma unroll
        for (int ks = 0; ks < 4; ks++) {           // K=128 in k32 steps
            const uint32_t kcol = (uint32_t)ks * 32;
            uint32_t ba[4][2], bq[4][2];
            #pragma unroll
            for (int ni = 0; ni < 4; ni++) {
                const uint32_t boff = bbase + ni * 1024 + ((kcol + bcoff) ^ bsw);
                ldsm2(ba[ni][0], ba[ni][1], pBa + boff);
                ldsm2(bq[ni][0], bq[ni][1], pBb + boff);
            }
            #pragma unroll
            for (int k = 0; k < 2; k++) {
                const uint32_t aoff = abase + ((kcol + acoff) ^ asw);
                {
                    uint32_t Aa[4];
                    ldsm4(Aa[0], Aa[1], Aa[2], Aa[3], Abuf + (2 * k + 0) * AP8 + aoff);
                    #pragma unroll
                    for (int ni = 0; ni < 4; ni++) {
                        mma_s8(acc1[k][ni], Aa, ba[ni]);
                        mma_s8(acc2[k][ni], Aa, bq[ni]);
                    }
                }
                {
                    uint32_t Ab[4];
                    ldsm4(Ab[0], Ab[1], Ab[2], Ab[3], Abuf + (2 * k + 1) * AP8 + aoff);
                    #pragma unroll
                    for (int ni = 0; ni < 4; ni++)
                        mma_s8(acc2[k][ni], Ab, ba[ni]);
                }
            }
        }

        // epilogue: dequantize + bias, float4 stores
        const int ibase = ihalf * 512 + c * 64;
        const int r0 = wm * 16 + crow, r1 = r0 + 8;
        const float stA0 = g_t8s[(b << 10) + ibase + r0];          // k0, row r0
        const float stA1 = g_t8s[8192 + (b << 10) + ibase + r0];   // k1, row r0
        const float stB0 = g_t8s[(b << 10) + ibase + r1];
        const float stB1 = g_t8s[8192 + (b << 10) + ibase + r1];
        #pragma unroll
        for (int ni = 0; ni < 4; ni++) {
            const int jj = j0 + wn * 32 + ni * 8 + 2 * cj;
            const float sA = g_hr8s[(b << 10) + jj];
            const float sB = g_hr8s[(b << 10) + jj + 1];
            {
                float4 v = make_float4(
                    bb0 + stA0 * sA * (16384.f * (float)acc1[0][ni][0] + 128.f * (float)acc2[0][ni][0]),
                    bb1 + stA1 * sA * (16384.f * (float)acc1[1][ni][0] + 128.f * (float)acc2[1][ni][0]),
                    bb0 + stA0 * sB * (16384.f * (float)acc1[0][ni][1] + 128.f * (float)acc2[0][ni][1]),
                    bb1 + stA1 * sB * (16384.f * (float)acc1[1][ni][1] + 128.f * (float)acc2[1][ni][1]));
                *(float4*)(out + ((size_t)b * N_ + ibase + r0) * N_ + jj) = v;
            }
            {
                float4 v = make_float4(
                    bb0 + stB0 * sA * (16384.f * (float)acc1[0][ni][2] + 128.f * (float)acc2[0][ni][2]),
                    bb1 + stB1 * sA * (16384.f * (float)acc1[1][ni][2] + 128.f * (float)acc2[1][ni][2]),
                    bb0 + stB0 * sB * (16384.f * (float)acc1[0][ni][3] + 128.f * (float)acc2[0][ni][3]),
                    bb1 + stB1 * sB * (16384.f * (float)acc1[1][ni][3] + 128.f * (float)acc2[1][ni][3]));
                *(float4*)(out + ((size_t)b * N_ + ibase + r1) * N_ + jj) = v;
            }
        }
    }
}

// =====================================================================
extern "C" void kernel_launch(void* const* d_in, const int* in_sizes, int n_in,
                              void* d_out, int out_size)
{
    (void)in_sizes; (void)n_in; (void)out_size;
    const float* x  = (const float*)d_in[0];
    const float* Wl = (const float*)d_in[1];
    const float* bl = (const float*)d_in[2];
    const float* Wr = (const float*)d_in[3];
    const float* br = (const float*)d_in[4];
    const float* Wb = (const float*)d_in[5];
    const float* bb = (const float*)d_in[6];

    const int smemH = 4 * HP;        // 196,608 B
    const int smemT = 4 * PB;        // 131,072 B
    const int smemC = PAIR_SMEM;     //  98,304 B
    cudaFuncSetAttribute(hidden_kernel, cudaFuncAttributeMaxDynamicSharedMemorySize, smemH);
    cudaFuncSetAttribute(tform_kernel,  cudaFuncAttributeMaxDynamicSharedMemorySize, smemT);
    cudaFuncSetAttribute(pair_kernel,   cudaFuncAttributeMaxDynamicSharedMemorySize, smemC);

    prep_kernel  <<<320, 256>>>(Wl, Wr, Wb);
    hidden_kernel<<<dim3(8, B_, 2), 256, smemH>>>(x, bl, br);
    tform_kernel <<<dim3(8, B_, 2), 256, smemT>>>();
    quant_kernel <<<3072, 256>>>();
    pair_kernel  <<<dim3(8, B_, 2), 512, smemC>>>(bb, (float2*)d_out);
}

// round 17
// speedup vs baseline: 2.1243x; 2.1243x over previous
#include <cuda_runtime.h>
#include <cuda_bf16.h>
#include <cstdint>

#define B_   8
#define N_   1024
#define NIN_ 64
#define H_   128
#define F_   192

typedef unsigned long long u64;

// ---------------- scratch (device globals) ----------------
__device__ __align__(16) char g_Wsw_hi[2 * 49152];   // W sides, 384B-pitch swizzled
__device__ __align__(16) char g_Wsw_lo[2 * 49152];
__device__ __align__(16) char g_WbT_hi[2 * 32768];   // W_bil^T per k, 256B-pitch swizzled
__device__ __align__(16) char g_WbT_lo[2 * 32768];
__device__ __align__(16) __nv_bfloat16 g_hlb_hi[B_ * N_ * H_];
__device__ __align__(16) __nv_bfloat16 g_hlb_lo[B_ * N_ * H_];
__device__ __align__(16) __nv_bfloat16 g_hr_hi[B_ * N_ * H_];
__device__ __align__(16) __nv_bfloat16 g_hr_lo[B_ * N_ * H_];
__device__ __align__(16) __nv_bfloat16 g_t_hi[2 * B_ * N_ * H_];
__device__ __align__(16) __nv_bfloat16 g_t_lo[2 * B_ * N_ * H_];

__device__ __forceinline__ uint32_t smem_u32(const void* p) {
    uint32_t a;
    asm("{ .reg .u64 t; cvta.to.shared.u64 t, %1; cvt.u32.u64 %0, t; }" : "=r"(a) : "l"(p));
    return a;
}
// ---------------- tensor-core primitives (no 'a'-suffix PTX) ----------------
__device__ __forceinline__ void ldsm4(uint32_t& a0, uint32_t& a1, uint32_t& a2, uint32_t& a3, uint32_t addr) {
    asm volatile("ldmatrix.sync.aligned.m8n8.x4.shared.b16 {%0,%1,%2,%3}, [%4];"
        : "=r"(a0), "=r"(a1), "=r"(a2), "=r"(a3) : "r"(addr));
}
__device__ __forceinline__ void ldsm2(uint32_t& b0, uint32_t& b1, uint32_t addr) {
    asm volatile("ldmatrix.sync.aligned.m8n8.x2.shared.b16 {%0,%1}, [%2];"
        : "=r"(b0), "=r"(b1) : "r"(addr));
}
__device__ __forceinline__ void mma_bf16(float* c, const uint32_t* a, const uint32_t* b) {
    asm volatile("mma.sync.aligned.m16n8k16.row.col.f32.bf16.bf16.f32 "
        "{%0,%1,%2,%3}, {%4,%5,%6,%7}, {%8,%9}, {%0,%1,%2,%3};"
        : "+f"(c[0]), "+f"(c[1]), "+f"(c[2]), "+f"(c[3])
        : "r"(a[0]), "r"(a[1]), "r"(a[2]), "r"(a[3]), "r"(b[0]), "r"(b[1]));
}
__device__ __forceinline__ void split_bf16(float v, __nv_bfloat16& hi, __nv_bfloat16& lo) {
    hi = __float2bfloat16_rn(v);
    lo = __float2bfloat16_rn(v - __bfloat162float(hi));
}
// ---------------- cp.async ----------------
__device__ __forceinline__ void cp16(uint32_t dst, const void* src) {
    asm volatile("cp.async.cg.shared.global [%0], [%1], 16;" :: "r"(dst), "l"(src));
}
__device__ __forceinline__ void cp_commit() { asm volatile("cp.async.commit_group;" ::: "memory"); }
__device__ __forceinline__ void cp_wait0()  { asm volatile("cp.async.wait_group 0;" ::: "memory"); }

// =====================================================================
// prep: W -> bf16 hi/lo planes, pre-swizzled (unchanged)
// =====================================================================
__global__ __launch_bounds__(256)
void prep_kernel(const float* __restrict__ Wl, const float* __restrict__ Wr,
                 const float* __restrict__ Wbil)
{
    const int t = blockIdx.x * 256 + threadIdx.x;
    if (t < 2 * H_ * F_) {
        int side = t / (H_ * F_), r = t % (H_ * F_);
        int h = r / F_, f = r % F_;
        float v = (side ? Wr : Wl)[r];
        __nv_bfloat16 hi, lo; split_bf16(v, hi, lo);
        uint32_t byte = (uint32_t)h * 384u + (((uint32_t)f * 2u) ^ (((uint32_t)h & 7u) << 4));
        *(__nv_bfloat16*)(g_Wsw_hi + side * 49152 + byte) = hi;
        *(__nv_bfloat16*)(g_Wsw_lo + side * 49152 + byte) = lo;
    } else if (t < 2 * H_ * F_ + 2 * H_ * H_) {
        int r = t - 2 * H_ * F_;
        int k = r / (H_ * H_), rr = r % (H_ * H_);
        int g = rr / H_, h = rr % H_;
        float v = Wbil[k * H_ * H_ + h * H_ + g];
        __nv_bfloat16 hi, lo; split_bf16(v, hi, lo);
        uint32_t byte = (uint32_t)g * 256u + (((uint32_t)h * 2u) ^ (((uint32_t)g & 7u) << 4));
        *(__nv_bfloat16*)(g_WbT_hi + k * 32768 + byte) = hi;
        *(__nv_bfloat16*)(g_WbT_lo + k * 32768 + byte) = lo;
    }
}

// =====================================================================
// Kernel A (HMMA, unchanged from r15)
// =====================================================================
#define HP 49152

__global__ __launch_bounds__(256, 1)
void hidden_kernel(const float* __restrict__ x,
                   const float* __restrict__ bl, const float* __restrict__ br)
{
    extern __shared__ char smc[];
    const int i0   = blockIdx.x * 128;
    const int b    = blockIdx.y;
    const int side = blockIdx.z;
    const int tid  = threadIdx.x;

    {
        const uint4* sh = (const uint4*)(g_Wsw_hi + side * HP);
        const uint4* sl = (const uint4*)(g_Wsw_lo + side * HP);
        uint4* dh = (uint4*)(smc + 2 * HP);
        uint4* dl = (uint4*)(smc + 3 * HP);
        #pragma unroll
        for (int it = 0; it < 12; it++) {
            dh[tid + it * 256] = sh[tid + it * 256];
            dl[tid + it * 256] = sl[tid + it * 256];
        }
    }
    const float* xb = x + (size_t)b * N_ * NIN_;
    #pragma unroll
    for (int seg = 0; seg < 3; seg++) {
        const int off = (seg == 0) ? 0 : (((seg == 1) == (side == 0)) ? -1 : 1);
        #pragma unroll 4
        for (int it = 0; it < 16; it++) {
            int idx = tid + it * 256;
            int m = idx >> 5, cp = idx & 31;
            int gi = i0 + m + off;
            float2 v = (gi >= 0 && gi < N_) ? *(const float2*)(xb + gi * NIN_ + cp * 2)
                                            : make_float2(0.f, 0.f);
            __nv_bfloat16 h0, l0, h1, l1;
            split_bf16(v.x, h0, l0); split_bf16(v.y, h1, l1);
            uint32_t byte = (uint32_t)m * 384u +
                (((uint32_t)(seg * 128 + cp * 4)) ^ (((uint32_t)m & 7u) << 4));
            *(__nv_bfloat162*)(smc + byte)      = __nv_bfloat162(h0, h1);
            *(__nv_bfloat162*)(smc + HP + byte) = __nv_bfloat162(l0, l1);
        }
    }
    __syncthreads();

    const int warp = tid >> 5, lane = tid & 31;
    const int wm = warp >> 2, wn = warp & 3;
    const int arowl = wm * 64 + ((lane >> 3) & 1) * 8 + (lane & 7);
    const uint32_t acoff = (lane >> 4) * 16;
    const uint32_t asw = (arowl & 7) << 4;
    const uint32_t abase = (uint32_t)arowl * 384;
    const int l16 = lane & 15;
    const int browl = wn * 32 + (l16 & 7);
    const uint32_t bcoff = ((l16 >> 3) & 1) * 16;
    const uint32_t bsw = (browl & 7) << 4;
    const uint32_t bbase = (uint32_t)browl * 384;

    const uint32_t sb = smem_u32(smc);
    const uint32_t pAhi = sb, pAlo = sb + HP, pBhi = sb + 2 * HP, pBlo = sb + 3 * HP;

    float acc[4][4][4];
    #pragma unroll
    for (int mi = 0; mi < 4; mi++)
        #pragma unroll
        for (int ni = 0; ni < 4; ni++)
            #pragma unroll
            for (int e = 0; e < 4; e++) acc[mi][ni][e] = 0.f;

    #pragma unroll 1
    for (int pass = 0; pass < 3; pass++) {
        const uint32_t pa = (pass == 2) ? pAlo : pAhi;
        const uint32_t pb = (pass == 1) ? pBlo : pBhi;
        #pragma unroll 4
        for (int ks = 0; ks < 12; ks++) {
            const uint32_t kcol = (uint32_t)ks * 32;
            uint32_t a[4][4], bf[4][2];
            #pragma unroll
            for (int mi = 0; mi < 4; mi++)
                ldsm4(a[mi][0], a[mi][1], a[mi][2], a[mi][3],
                      pa + abase + mi * 16 * 384 + ((kcol + acoff) ^ asw));
            #pragma unroll
            for (int ni = 0; ni < 4; ni++)
                ldsm2(bf[ni][0], bf[ni][1],
                      pb + bbase + ni * 8 * 384 + ((kcol + bcoff) ^ bsw));
            #pragma unroll
            for (int mi = 0; mi < 4; mi++)
                #pragma unroll
                for (int ni = 0; ni < 4; ni++)
                    mma_bf16(acc[mi][ni], a[mi], bf[ni]);
        }
    }

    const int crow = lane >> 2, cj = lane & 3;
    const float* bias = side ? br : bl;
    __nv_bfloat16* dhi = side ? g_hr_hi : g_hlb_hi;
    __nv_bfloat16* dlo = side ? g_hr_lo : g_hlb_lo;
    #pragma unroll
    for (int mi = 0; mi < 4; mi++) {
        #pragma unroll
        for (int ni = 0; ni < 4; ni++) {
            const int h0 = wn * 32 + ni * 8 + 2 * cj;
            const float2 bv = *(const float2*)(bias + h0);
            #pragma unroll
            for (int half = 0; half < 2; half++) {
                const int r = wm * 64 + mi * 16 + crow + half * 8;
                float v0 = fmaxf(acc[mi][ni][2 * half + 0] + bv.x, 0.f);
                float v1 = fmaxf(acc[mi][ni][2 * half + 1] + bv.y, 0.f);
                __nv_bfloat16 h0b, l0b, h1b, l1b;
                split_bf16(v0, h0b, l0b); split_bf16(v1, h1b, l1b);
                const size_t o = ((size_t)b * N_ + i0 + r) * H_ + h0;
                *(__nv_bfloat162*)(dhi + o) = __nv_bfloat162(h0b, h1b);
                *(__nv_bfloat162*)(dlo + o) = __nv_bfloat162(l0b, l1b);
            }
        }
    }
}

// =====================================================================
// Kernel B (HMMA, unchanged from r15)
// =====================================================================
#define PB 32768

__device__ __forceinline__ void load_plane(char* dst, const __nv_bfloat16* src, int tid)
{
    const uint4* s = (const uint4*)src;
    #pragma unroll
    for (int it = 0; it < 8; it++) {
        int idx = tid + it * 256;
        int row = idx >> 4, c16 = idx & 15;
        uint32_t byte = row * 256 + ((c16 * 16) ^ ((row & 7) << 4));
        *(uint4*)(dst + byte) = s[idx];
    }
}

__global__ __launch_bounds__(256, 1)
void tform_kernel()
{
    extern __shared__ char smc[];
    const int i0 = blockIdx.x * 128;
    const int b  = blockIdx.y;
    const int k  = blockIdx.z;
    const int tid = threadIdx.x;

    const size_t arow = ((size_t)b * N_ + i0) * H_;
    load_plane(smc + 0 * PB, g_hlb_hi + arow, tid);
    load_plane(smc + 1 * PB, g_hlb_lo + arow, tid);
    {
        const uint4* sh = (const uint4*)(g_WbT_hi + k * PB);
        const uint4* sl = (const uint4*)(g_WbT_lo + k * PB);
        uint4* dh = (uint4*)(smc + 2 * PB);
        uint4* dl = (uint4*)(smc + 3 * PB);
        #pragma unroll
        for (int it = 0; it < 8; it++) {
            dh[tid + it * 256] = sh[tid + it * 256];
            dl[tid + it * 256] = sl[tid + it * 256];
        }
    }
    __syncthreads();

    const int warp = tid >> 5, lane = tid & 31;
    const int wm = warp >> 2, wn = warp & 3;
    const int arowl = wm * 64 + ((lane >> 3) & 1) * 8 + (lane & 7);
    const uint32_t acoff = (lane >> 4) * 16;
    const uint32_t asw = (arowl & 7) << 4;
    const uint32_t abase = (uint32_t)arowl * 256;
    const int l16 = lane & 15;
    const int browl = wn * 32 + (l16 & 7);
    const uint32_t bcoff = ((l16 >> 3) & 1) * 16;
    const uint32_t bsw = (browl & 7) << 4;
    const uint32_t bbase = (uint32_t)browl * 256;

    const uint32_t sb = smem_u32(smc);
    const uint32_t pAhi = sb, pAlo = sb + PB, pBhi = sb + 2 * PB, pBlo = sb + 3 * PB;

    float acc[4][4][4];
    #pragma unroll
    for (int mi = 0; mi < 4; mi++)
        #pragma unroll
        for (int ni = 0; ni < 4; ni++)
            #pragma unroll
            for (int e = 0; e < 4; e++) acc[mi][ni][e] = 0.f;

    #pragma unroll 1
    for (int pass = 0; pass < 3; pass++) {
        const uint32_t pa = (pass == 2) ? pAlo : pAhi;
        const uint32_t pb = (pass == 1) ? pBlo : pBhi;
        #pragma unroll 4
        for (int ks = 0; ks < 8; ks++) {
            const uint32_t kcol = (uint32_t)ks * 32;
            uint32_t a[4][4], bf[4][2];
            #pragma unroll
            for (int mi = 0; mi < 4; mi++)
                ldsm4(a[mi][0], a[mi][1], a[mi][2], a[mi][3],
                      pa + abase + mi * 4096 + ((kcol + acoff) ^ asw));
            #pragma unroll
            for (int ni = 0; ni < 4; ni++)
                ldsm2(bf[ni][0], bf[ni][1],
                      pb + bbase + ni * 2048 + ((kcol + bcoff) ^ bsw));
            #pragma unroll
            for (int mi = 0; mi < 4; mi++)
                #pragma unroll
                for (int ni = 0; ni < 4; ni++)
                    mma_bf16(acc[mi][ni], a[mi], bf[ni]);
        }
    }

    const int crow = lane >> 2, cj = lane & 3;
    __nv_bfloat16* dhi = g_t_hi + (size_t)k * B_ * N_ * H_;
    __nv_bfloat16* dlo = g_t_lo + (size_t)k * B_ * N_ * H_;
    #pragma unroll
    for (int mi = 0; mi < 4; mi++) {
        #pragma unroll
        for (int ni = 0; ni < 4; ni++) {
            const int g0 = wn * 32 + ni * 8 + 2 * cj;
            #pragma unroll
            for (int half = 0; half < 2; half++) {
                const int r = wm * 64 + mi * 16 + crow + half * 8;
                float v0 = acc[mi][ni][2 * half + 0];
                float v1 = acc[mi][ni][2 * half + 1];
                __nv_bfloat16 h0b, l0b, h1b, l1b;
                split_bf16(v0, h0b, l0b); split_bf16(v1, h1b, l1b);
                const size_t o = ((size_t)b * N_ + i0 + r) * H_ + g0;
                *(__nv_bfloat162*)(dhi + o) = __nv_bfloat162(h0b, h1b);
                *(__nv_bfloat162*)(dlo + o) = __nv_bfloat162(l0b, l1b);
            }
        }
    }
}

// =====================================================================
// Kernel C v6: r15 bf16 pipelined pair GEMM + B-fragment ping-pong.
//   512 threads, 4x4 warps; per ks, next ks's B frags are loaded while
//   current ks's 24 MMAs execute (fully unrolled, reg ping-pong).
// =====================================================================
#define PAIR_SMEM 196608
#define SUBP 16384            // 64 rows x 256B sub-plane

__device__ __forceinline__ void issue_A_chunk(uint32_t dstbase, int b, int i0c, int tid)
{
    const size_t bnh = (size_t)B_ * N_ * H_;
    const size_t rowbase = ((size_t)b * N_ + i0c) * H_;
    #pragma unroll
    for (int it = 0; it < 8; it++) {
        int idx = tid + it * 512;                 // 4096 x 16B
        int sub = idx >> 10;                      // 0..3 : k0hi,k0lo,k1hi,k1lo
        int k = sub >> 1, p = sub & 1;
        int r = (idx >> 4) & 63, c16 = idx & 15;
        const __nv_bfloat16* src = (p ? g_t_lo : g_t_hi) + k * bnh + rowbase + (size_t)r * H_ + c16 * 8;
        uint32_t dst = dstbase + sub * SUBP + r * 256 + ((c16 * 16) ^ ((r & 7) << 4));
        cp16(dst, src);
    }
}

__global__ __launch_bounds__(512, 1)
void pair_kernel(const float* __restrict__ bbil, float2* __restrict__ out)
{
    extern __shared__ char smc[];
    const uint32_t sbase = smem_u32(smc);
    const int j0    = blockIdx.x * 128;
    const int b     = blockIdx.y;
    const int ihalf = blockIdx.z;
    const int tid = threadIdx.x;
    const int warp = tid >> 5, lane = tid & 31;
    const int wm = warp >> 2, wn = warp & 3;     // 4(m) x 4(n)

    // --- B planes (hr hi/lo) via cp.async, swizzled ---
    {
        #pragma unroll
        for (int it = 0; it < 8; it++) {
            int idx = tid + it * 512;             // 4096 x 16B
            int p = idx >> 11;                    // 0 hi, 1 lo
            int r = (idx >> 4) & 127, c16 = idx & 15;
            const __nv_bfloat16* src = (p ? g_hr_lo : g_hr_hi) + ((size_t)b * N_ + j0 + r) * H_ + c16 * 8;
            uint32_t dst = sbase + p * PB + r * 256 + ((c16 * 16) ^ ((r & 7) << 4));
            cp16(dst, src);
        }
    }
    issue_A_chunk(sbase + 65536, b, ihalf * 512, tid);
    cp_commit();

    // lane geometry (identical to r15)
    const int arowl = wm * 16 + ((lane >> 3) & 1) * 8 + (lane & 7);
    const uint32_t acoff = (lane >> 4) * 16;
    const uint32_t asw = (arowl & 7) << 4;
    const uint32_t abase = (uint32_t)arowl * 256;
    const int l16 = lane & 15;
    const int browl = wn * 32 + (l16 & 7);
    const uint32_t bcoff = ((l16 >> 3) & 1) * 16;
    const uint32_t bsw = (browl & 7) << 4;
    const uint32_t bbase = (uint32_t)browl * 256;
    const uint32_t pBhi = sbase, pBlo = sbase + PB;

    const float bb0 = bbil[0], bb1 = bbil[1];
    const int crow = lane >> 2, cj = lane & 3;

    #pragma unroll 1
    for (int c = 0; c < 8; c++) {
        cp_wait0();
        __syncthreads();                           // buf[c&1] full, prior reads done
        if (c < 7) {
            issue_A_chunk(sbase + 65536 + ((c + 1) & 1) * 65536, b, ihalf * 512 + (c + 1) * 64, tid);
            cp_commit();
        }
        const uint32_t Abuf = sbase + 65536 + (c & 1) * 65536;

        float acc[2][4][4];                        // [k][ni][elem]
        #pragma unroll
        for (int k = 0; k < 2; k++)
            #pragma unroll
            for (int ni = 0; ni < 4; ni++)
                #pragma unroll
                for (int e = 0; e < 4; e++) acc[k][ni][e] = 0.f;

        // B-fragment ping-pong: slot ks&1 in use, slot (ks+1)&1 being filled
        uint32_t bh[2][4][2], blf[2][4][2];
        #pragma unroll
        for (int ni = 0; ni < 4; ni++) {
            const uint32_t boff = bbase + ni * 2048 + ((0 + bcoff) ^ bsw);
            ldsm2(bh[0][ni][0],  bh[0][ni][1],  pBhi + boff);
            ldsm2(blf[0][ni][0], blf[0][ni][1], pBlo + boff);
        }

        #pragma unroll
        for (int ks = 0; ks < 8; ks++) {
            const int cur = ks & 1, nxt = cur ^ 1;
            if (ks < 7) {
                const uint32_t kcoln = (uint32_t)(ks + 1) * 32;
                #pragma unroll
                for (int ni = 0; ni < 4; ni++) {
                    const uint32_t boff = bbase + ni * 2048 + ((kcoln + bcoff) ^ bsw);
                    ldsm2(bh[nxt][ni][0],  bh[nxt][ni][1],  pBhi + boff);
                    ldsm2(blf[nxt][ni][0], blf[nxt][ni][1], pBlo + boff);
                }
            }
            const uint32_t kcol = (uint32_t)ks * 32;
            #pragma unroll
            for (int k = 0; k < 2; k++) {
                const uint32_t pAhi = Abuf + (2 * k + 0) * SUBP;
                const uint32_t pAlo = Abuf + (2 * k + 1) * SUBP;
                {
                    uint32_t ah[4];
                    ldsm4(ah[0], ah[1], ah[2], ah[3],
                          pAhi + abase + ((kcol + acoff) ^ asw));
                    #pragma unroll
                    for (int ni = 0; ni < 4; ni++) {
                        mma_bf16(acc[k][ni], ah, bh[cur][ni]);
                        mma_bf16(acc[k][ni], ah, blf[cur][ni]);
                    }
                }
                {
                    uint32_t al[4];
                    ldsm4(al[0], al[1], al[2], al[3],
                          pAlo + abase + ((kcol + acoff) ^ asw));
                    #pragma unroll
                    for (int ni = 0; ni < 4; ni++)
                        mma_bf16(acc[k][ni], al, bh[cur][ni]);
                }
            }
        }

        // epilogue for this chunk
        const int ibase = ihalf * 512 + c * 64;
        #pragma unroll
        for (int ni = 0; ni < 4; ni++) {
            const int j2 = wn * 16 + ni * 4 + cj;
            const int jj = j0 + j2 * 2;
            {
                const int r = wm * 16 + crow;
                float4 v = make_float4(acc[0][ni][0] + bb0, acc[1][ni][0] + bb1,
                                       acc[0][ni][1] + bb0, acc[1][ni][1] + bb1);
                *(float4*)(out + ((size_t)b * N_ + ibase + r) * N_ + jj) = v;
            }
            {
                const int r = wm * 16 + crow + 8;
                float4 v = make_float4(acc[0][ni][2] + bb0, acc[1][ni][2] + bb1,
                                       acc[0][ni][3] + bb0, acc[1][ni][3] + bb1);
                *(float4*)(out + ((size_t)b * N_ + ibase + r) * N_ + jj) = v;
            }
        }
    }
}

// =====================================================================
extern "C" void kernel_launch(void* const* d_in, const int* in_sizes, int n_in,
                              void* d_out, int out_size)
{
    (void)in_sizes; (void)n_in; (void)out_size;
    const float* x  = (const float*)d_in[0];
    const float* Wl = (const float*)d_in[1];
    const float* bl = (const float*)d_in[2];
    const float* Wr = (const float*)d_in[3];
    const float* br = (const float*)d_in[4];
    const float* Wb = (const float*)d_in[5];
    const float* bb = (const float*)d_in[6];

    const int smemH = 4 * HP;        // 196,608 B
    const int smemT = 4 * PB;        // 131,072 B
    const int smemC = PAIR_SMEM;     // 196,608 B
    cudaFuncSetAttribute(hidden_kernel, cudaFuncAttributeMaxDynamicSharedMemorySize, smemH);
    cudaFuncSetAttribute(tform_kernel,  cudaFuncAttributeMaxDynamicSharedMemorySize, smemT);
    cudaFuncSetAttribute(pair_kernel,   cudaFuncAttributeMaxDynamicSharedMemorySize, smemC);

    prep_kernel  <<<320, 256>>>(Wl, Wr, Wb);
    hidden_kernel<<<dim3(8, B_, 2), 256, smemH>>>(x, bl, br);
    tform_kernel <<<dim3(8, B_, 2), 256, smemT>>>();
    pair_kernel  <<<dim3(8, B_, 2), 512, smemC>>>(bb, (float2*)d_out);
}